// round 1
// baseline (speedup 1.0000x reference)
#include <cuda_runtime.h>

#define D     256
#define S     2048
#define BATCH 8
#define M_TOTAL (BATCH * S)   // 16384
#define KC    (3 * D)         // 768
#define PART  16

// Scratch (static device globals — no runtime allocation)
__device__ float g_part[BATCH][PART][D];
__device__ float g_total[BATCH][D];
__device__ float g_z[(long)M_TOTAL * KC];   // 48 MB
__device__ float g_wcat[KC * D];            // 768 x 256

// ---------------------------------------------------------------------------
// Kernel 1a: partial column sums over S (deterministic two-stage reduce)
// ---------------------------------------------------------------------------
__global__ void colsum_part(const float* __restrict__ x) {
    int b = blockIdx.x, p = blockIdx.y, i = threadIdx.x;
    const int chunk = S / PART;                // 128
    const float* xp = x + ((long)b * S + (long)p * chunk) * D + i;
    float acc = 0.f;
    #pragma unroll 8
    for (int s = 0; s < chunk; ++s) acc += xp[(long)s * D];
    g_part[b][p][i] = acc;
}

__global__ void colsum_reduce() {
    int b = blockIdx.x, i = threadIdx.x;
    float acc = 0.f;
    #pragma unroll
    for (int p = 0; p < PART; ++p) acc += g_part[b][p][i];
    g_total[b][i] = acc;
}

// ---------------------------------------------------------------------------
// Kernel 2: build z = [z0 | z1 | x]  (relation-contracted aggregates)
//   agg0 = x[t+1]                      (or 0 at boundary)
//   agg1 = mean(x[t], x[t+2])
//   agg2 = mean(x[t-1], x[t+3])
//   agg3 = (total - sum(x[t-1..t+3])) / deg3
//   z_b  = sum_r comp[r,b] * agg_r
// ---------------------------------------------------------------------------
__global__ void build_z(const float* __restrict__ x, const float* __restrict__ comp) {
    int t = blockIdx.x, b = blockIdx.y, i = threadIdx.x;
    const float* xb = x + (long)b * S * D;

    float xm1 = (t >= 1)    ? xb[(long)(t - 1) * D + i] : 0.f;
    float x0  =               xb[(long)t       * D + i];
    float xp1 = (t + 1 < S) ? xb[(long)(t + 1) * D + i] : 0.f;
    float xp2 = (t + 2 < S) ? xb[(long)(t + 2) * D + i] : 0.f;
    float xp3 = (t + 3 < S) ? xb[(long)(t + 3) * D + i] : 0.f;

    float wsum = xm1 + x0 + xp1 + xp2 + xp3;
    int cnt = 1 + (t >= 1) + (t + 1 < S) + (t + 2 < S) + (t + 3 < S);

    float agg0 = xp1;  // deg0 = 1 iff t+1<S; xp1 already zeroed otherwise
    float n1 = 1.f + (float)(t + 2 < S);
    float agg1 = (x0 + xp2) / n1;
    int n2 = (t >= 1) + (t + 3 < S);
    float agg2 = n2 ? (xm1 + xp3) / (float)n2 : 0.f;
    float deg3 = (float)(S - cnt);
    float agg3 = (g_total[b][i] - wsum) / deg3;

    // comp[r, cb] at comp[r*2 + cb]
    float z0 = comp[0] * agg0 + comp[2] * agg1 + comp[4] * agg2 + comp[6] * agg3;
    float z1 = comp[1] * agg0 + comp[3] * agg1 + comp[5] * agg2 + comp[7] * agg3;

    long row = (long)(b * S + t) * KC;
    g_z[row + i]         = z0;
    g_z[row + D + i]     = z1;
    g_z[row + 2 * D + i] = x0;
}

// ---------------------------------------------------------------------------
// Kernel 3: pack W = [basis0 ; basis1 ; root]  (768 x 256)
// ---------------------------------------------------------------------------
__global__ void pack_w(const float* __restrict__ basis, const float* __restrict__ root) {
    int idx = blockIdx.x * blockDim.x + threadIdx.x;   // 0 .. KC*D-1
    g_wcat[idx] = (idx < 2 * D * D) ? basis[idx] : root[idx - 2 * D * D];
}

// ---------------------------------------------------------------------------
// Kernel 4: SGEMM  out[M,256] = g_z[M,768] @ g_wcat[768,256] + bias
// 128x128 CTA tile, BK=16, 256 threads, 8x8 per-thread tile
// ---------------------------------------------------------------------------
#define BM 128
#define BN 128
#define BK 16
#define TM 8
#define TN 8

__global__ __launch_bounds__(256, 2)
void sgemm_bias(const float* __restrict__ bias, float* __restrict__ out) {
    __shared__ float As[BK][BM];   // A stored k-major (transposed)
    __shared__ float Bs[BK][BN];

    int tid = threadIdx.x;
    int block_row = blockIdx.y * BM;
    int block_col = blockIdx.x * BN;
    int tr = (tid / 16) * TM;      // row within tile
    int tc = (tid % 16) * TN;      // col within tile

    const float* Aptr = g_z + (long)block_row * KC;
    const float* Bptr = g_wcat + block_col;

    float acc[TM][TN];
    #pragma unroll
    for (int m = 0; m < TM; ++m)
        #pragma unroll
        for (int n = 0; n < TN; ++n) acc[m][n] = 0.f;

    for (int k0 = 0; k0 < KC; k0 += BK) {
        // Load A tile: 128x16 floats = 512 float4; 2 per thread. Store transposed.
        #pragma unroll
        for (int l = 0; l < 2; ++l) {
            int idx = tid + l * 256;        // 0..511
            int m  = idx >> 2;              // row 0..127
            int kq = (idx & 3) << 2;        // col 0,4,8,12
            float4 v = *(const float4*)(Aptr + (long)m * KC + k0 + kq);
            As[kq + 0][m] = v.x;
            As[kq + 1][m] = v.y;
            As[kq + 2][m] = v.z;
            As[kq + 3][m] = v.w;
        }
        // Load B tile: 16x128 floats = 512 float4; 2 per thread.
        #pragma unroll
        for (int l = 0; l < 2; ++l) {
            int idx = tid + l * 256;
            int kk = idx >> 5;              // row 0..15
            int nq = (idx & 31) << 2;       // col 0..124
            *(float4*)&Bs[kk][nq] = *(const float4*)(Bptr + (long)(k0 + kk) * D + nq);
        }
        __syncthreads();

        #pragma unroll
        for (int k = 0; k < BK; ++k) {
            float4 a0 = *(const float4*)&As[k][tr];
            float4 a1 = *(const float4*)&As[k][tr + 4];
            float4 b0 = *(const float4*)&Bs[k][tc];
            float4 b1 = *(const float4*)&Bs[k][tc + 4];
            float ra[TM] = {a0.x, a0.y, a0.z, a0.w, a1.x, a1.y, a1.z, a1.w};
            float rb[TN] = {b0.x, b0.y, b0.z, b0.w, b1.x, b1.y, b1.z, b1.w};
            #pragma unroll
            for (int m = 0; m < TM; ++m)
                #pragma unroll
                for (int n = 0; n < TN; ++n)
                    acc[m][n] += ra[m] * rb[n];
        }
        __syncthreads();
    }

    // Epilogue: add bias, store
    #pragma unroll
    for (int m = 0; m < TM; ++m) {
        int row = block_row + tr + m;
        #pragma unroll
        for (int n = 0; n < TN; n += 4) {
            int col = block_col + tc + n;
            float4 v;
            v.x = acc[m][n + 0] + bias[col + 0];
            v.y = acc[m][n + 1] + bias[col + 1];
            v.z = acc[m][n + 2] + bias[col + 2];
            v.w = acc[m][n + 3] + bias[col + 3];
            *(float4*)(out + (long)row * D + col) = v;
        }
    }
}

// ---------------------------------------------------------------------------
extern "C" void kernel_launch(void* const* d_in, const int* in_sizes, int n_in,
                              void* d_out, int out_size) {
    const float* x     = (const float*)d_in[0];
    const float* comp  = (const float*)d_in[1];
    const float* basis = (const float*)d_in[2];
    const float* root  = (const float*)d_in[3];
    const float* bias  = (const float*)d_in[4];
    float* out = (float*)d_out;

    colsum_part<<<dim3(BATCH, PART), D>>>(x);
    colsum_reduce<<<BATCH, D>>>();
    pack_w<<<(KC * D) / 256, 256>>>(basis, root);
    build_z<<<dim3(S, BATCH), D>>>(x, comp);
    sgemm_bias<<<dim3(D / BN, M_TOTAL / BM), 256>>>(bias, out);
}

// round 3
// speedup vs baseline: 2.1298x; 2.1298x over previous
#include <cuda_runtime.h>
#include <cuda_fp16.h>
#include <cstdint>

#define D     256
#define S     2048
#define BATCH 8
#define M_TOTAL (BATCH * S)   // 16384
#define KC    (3 * D)         // 768
#define PART  16

#define NCHUNK 12             // K chunks of 64
#define ABLK   32768          // one (tile,chunk) block: [hi 128x64 fp16][lo 128x64 fp16]
#define MTILES (M_TOTAL / 128)  // 128
#define STAGE_BYTES 65536     // A block (32K) + B block (32K)
#define GEMM_SMEM (2 * STAGE_BYTES)  // 128 KB

// ---------------- scratch (static device globals) ----------------
__device__ float g_part[BATCH][PART][D];
__device__ float g_total[BATCH][D];
// A: [mtile][chunk][hi/lo][row 128][k 64], swizzled rows. 128*12*32768 = 48 MB
__device__ __align__(16) unsigned char g_A[(size_t)MTILES * NCHUNK * ABLK];
// B: [nhalf][chunk][hi/lo][n 128][k 64]  (W transposed to [N][K]). 768 KB
__device__ __align__(16) unsigned char g_B[(size_t)2 * NCHUNK * ABLK];

// ---------------- helpers ----------------
__device__ __forceinline__ uint32_t smem_u32(const void* p) {
    uint32_t a;
    asm("{ .reg .u64 t; cvta.to.shared.u64 t, %1; cvt.u32.u64 %0, t; }" : "=r"(a) : "l"(p));
    return a;
}

// swizzled byte offset inside a 128x64-half (16 KB) block
__device__ __forceinline__ uint32_t swoff(int row, int kk) {
    return (uint32_t)(row * 128 + ((((kk >> 3) ^ (row & 7)) << 4)) + (kk & 7) * 2);
}

__device__ __forceinline__ void store_hl(unsigned char* blk, int row, int kk, float v) {
    __half h = __float2half_rn(v);
    __half l = __float2half_rn(v - __half2float(h));
    uint32_t o = swoff(row, kk);
    *(__half*)(blk + o) = h;
    *(__half*)(blk + 16384 + o) = l;
}

__device__ __forceinline__ void cp16(uint32_t dst, const void* src) {
    asm volatile("cp.async.cg.shared.global [%0], [%1], 16;"
        :: "r"(dst), "l"(__cvta_generic_to_global(src)));
}

__device__ __forceinline__ void ldm_x4(uint32_t addr, uint32_t* f) {
    asm volatile("ldmatrix.sync.aligned.m8n8.x4.shared.b16 {%0,%1,%2,%3}, [%4];"
        : "=r"(f[0]), "=r"(f[1]), "=r"(f[2]), "=r"(f[3]) : "r"(addr));
}

// A fragment source address (m16 x k16 tile at (r0,k0)); matrices a0,a1,a2,a3
__device__ __forceinline__ uint32_t a_addr(uint32_t base, int r0, int k0, int lane) {
    int i = lane & 7, seg = lane >> 3;
    int row = r0 + i + ((seg & 1) << 3);
    int kk = k0 + ((seg >> 1) << 3);
    return base + (uint32_t)(row * 128) + ((((kk >> 3) ^ (row & 7)) << 4));
}
// B fragment source address (n16 x k16 at (n0,k0)); order (n0,k0),(n0,k0+8),(n0+8,k0),(n0+8,k0+8)
__device__ __forceinline__ uint32_t b_addr(uint32_t base, int n0, int k0, int lane) {
    int i = lane & 7, seg = lane >> 3;
    int row = n0 + i + ((seg >> 1) << 3);
    int kk = k0 + ((seg & 1) << 3);
    return base + (uint32_t)(row * 128) + ((((kk >> 3) ^ (row & 7)) << 4));
}

__device__ __forceinline__ void mma16816(float* c, const uint32_t* a, uint32_t b0, uint32_t b1) {
    asm volatile("mma.sync.aligned.m16n8k16.row.col.f32.f16.f16.f32 "
        "{%0,%1,%2,%3}, {%4,%5,%6,%7}, {%8,%9}, {%0,%1,%2,%3};"
        : "+f"(c[0]), "+f"(c[1]), "+f"(c[2]), "+f"(c[3])
        : "r"(a[0]), "r"(a[1]), "r"(a[2]), "r"(a[3]), "r"(b0), "r"(b1));
}

// ---------------------------------------------------------------------------
// Kernel 1: column sums (two-stage, deterministic)
// ---------------------------------------------------------------------------
__global__ void colsum_part(const float* __restrict__ x) {
    int b = blockIdx.x, p = blockIdx.y, i = threadIdx.x;
    const int chunk = S / PART;
    const float* xp = x + ((long)b * S + (long)p * chunk) * D + i;
    float acc = 0.f;
    #pragma unroll 8
    for (int s = 0; s < chunk; ++s) acc += xp[(long)s * D];
    g_part[b][p][i] = acc;
}
__global__ void colsum_reduce() {
    int b = blockIdx.x, i = threadIdx.x;
    float acc = 0.f;
    #pragma unroll
    for (int p = 0; p < PART; ++p) acc += g_part[b][p][i];
    g_total[b][i] = acc;
}

// ---------------------------------------------------------------------------
// Kernel 2: build z = [z0 | z1 | x], split fp16 hi/lo, packed+swizzled blocks
// ---------------------------------------------------------------------------
__global__ void build_z_pack(const float* __restrict__ x, const float* __restrict__ comp) {
    int t = blockIdx.x, b = blockIdx.y, i = threadIdx.x;
    const float* xb = x + (long)b * S * D;

    float xm1 = (t >= 1)    ? xb[(long)(t - 1) * D + i] : 0.f;
    float x0  =               xb[(long)t       * D + i];
    float xp1 = (t + 1 < S) ? xb[(long)(t + 1) * D + i] : 0.f;
    float xp2 = (t + 2 < S) ? xb[(long)(t + 2) * D + i] : 0.f;
    float xp3 = (t + 3 < S) ? xb[(long)(t + 3) * D + i] : 0.f;

    float wsum = xm1 + x0 + xp1 + xp2 + xp3;
    int cnt = 1 + (t >= 1) + (t + 1 < S) + (t + 2 < S) + (t + 3 < S);

    float agg0 = xp1;
    float n1 = 1.f + (float)(t + 2 < S);
    float agg1 = (x0 + xp2) / n1;
    int n2 = (t >= 1) + (t + 3 < S);
    float agg2 = n2 ? (xm1 + xp3) / (float)n2 : 0.f;
    float deg3 = (float)(S - cnt);
    float agg3 = (g_total[b][i] - wsum) / deg3;

    float z0 = comp[0] * agg0 + comp[2] * agg1 + comp[4] * agg2 + comp[6] * agg3;
    float z1 = comp[1] * agg0 + comp[3] * agg1 + comp[5] * agg2 + comp[7] * agg3;

    int m = b * S + t;
    int mtile = m >> 7, r = m & 127;
    size_t tb = (size_t)(mtile * NCHUNK) * ABLK;

    // z0 at k=i, z1 at k=256+i, x at k=512+i
    int k;
    k = i;         store_hl(g_A + tb + (size_t)(k >> 6) * ABLK, r, k & 63, z0);
    k = 256 + i;   store_hl(g_A + tb + (size_t)(k >> 6) * ABLK, r, k & 63, z1);
    k = 512 + i;   store_hl(g_A + tb + (size_t)(k >> 6) * ABLK, r, k & 63, x0);
}

// ---------------------------------------------------------------------------
// Kernel 3: pack weights W[k][n] -> B[nhalf][chunk][hi/lo][n%128][k%64]
// ---------------------------------------------------------------------------
__global__ void convert_w(const float* __restrict__ basis, const float* __restrict__ root) {
    int k = blockIdx.x;          // 0..767
    int n = threadIdx.x;         // 0..255
    float v = (k < 2 * D) ? basis[(size_t)k * D + n] : root[(size_t)(k - 2 * D) * D + n];
    int nhalf = n >> 7, row = n & 127, chunk = k >> 6, kk = k & 63;
    store_hl(g_B + (size_t)(nhalf * NCHUNK + chunk) * ABLK, row, kk, v);
}

// ---------------------------------------------------------------------------
// Kernel 4: HMMA split-fp16 GEMM  out[16384,256] = z @ W + bias
// grid (2 nhalf, 128 mtile), 256 threads, CTA tile 128x128, BK=64, 2 stages
// ---------------------------------------------------------------------------
__device__ __forceinline__ void load_stage(uint32_t sbase, const unsigned char* A,
                                           const unsigned char* B, int tid) {
    #pragma unroll
    for (int i = 0; i < 8; ++i) {
        uint32_t off = (uint32_t)tid * 16 + (uint32_t)i * 4096;
        cp16(sbase + off, A + off);
        cp16(sbase + 32768 + off, B + off);
    }
}

__global__ void __launch_bounds__(256, 1)
gemm_hmma(const float* __restrict__ bias, float* __restrict__ out) {
    extern __shared__ unsigned char smem[];
    uint32_t sbase = smem_u32(smem);
    int tid = threadIdx.x, lane = tid & 31, wid = tid >> 5;
    int wm = wid >> 1, wn = wid & 1;      // 4 x 2 warp grid; warp tile 32 x 64
    int nhalf = blockIdx.x, mtile = blockIdx.y;

    const unsigned char* Asrc = g_A + (size_t)(mtile * NCHUNK) * ABLK;
    const unsigned char* Bsrc = g_B + (size_t)(nhalf * NCHUNK) * ABLK;

    load_stage(sbase, Asrc, Bsrc, tid);
    asm volatile("cp.async.commit_group;");

    float acc[2][8][4];
    #pragma unroll
    for (int mt = 0; mt < 2; ++mt)
        #pragma unroll
        for (int nt = 0; nt < 8; ++nt)
            #pragma unroll
            for (int q = 0; q < 4; ++q) acc[mt][nt][q] = 0.f;

    for (int c = 0; c < NCHUNK; ++c) {
        if (c + 1 < NCHUNK) {
            load_stage(sbase + (uint32_t)((c + 1) & 1) * STAGE_BYTES,
                       Asrc + (size_t)(c + 1) * ABLK, Bsrc + (size_t)(c + 1) * ABLK, tid);
            asm volatile("cp.async.commit_group;");
            asm volatile("cp.async.wait_group 1;");
        } else {
            asm volatile("cp.async.wait_group 0;");
        }
        __syncthreads();

        uint32_t st = sbase + (uint32_t)(c & 1) * STAGE_BYTES;
        uint32_t Ah = st, Al = st + 16384, Bh = st + 32768, Bl = st + 49152;

        #pragma unroll
        for (int k16 = 0; k16 < 4; ++k16) {
            int k0 = k16 * 16;
            uint32_t ah[2][4], al[2][4], bh[4][4], bl[4][4];
            #pragma unroll
            for (int mt = 0; mt < 2; ++mt) {
                ldm_x4(a_addr(Ah, wm * 32 + mt * 16, k0, lane), ah[mt]);
                ldm_x4(a_addr(Al, wm * 32 + mt * 16, k0, lane), al[mt]);
            }
            #pragma unroll
            for (int g = 0; g < 4; ++g) {
                ldm_x4(b_addr(Bh, wn * 64 + g * 16, k0, lane), bh[g]);
                ldm_x4(b_addr(Bl, wn * 64 + g * 16, k0, lane), bl[g]);
            }
            #pragma unroll
            for (int mt = 0; mt < 2; ++mt)
                #pragma unroll
                for (int g = 0; g < 4; ++g) {
                    mma16816(acc[mt][2 * g],     ah[mt], bh[g][0], bh[g][1]);
                    mma16816(acc[mt][2 * g + 1], ah[mt], bh[g][2], bh[g][3]);
                    mma16816(acc[mt][2 * g],     ah[mt], bl[g][0], bl[g][1]);
                    mma16816(acc[mt][2 * g + 1], ah[mt], bl[g][2], bl[g][3]);
                    mma16816(acc[mt][2 * g],     al[mt], bh[g][0], bh[g][1]);
                    mma16816(acc[mt][2 * g + 1], al[mt], bh[g][2], bh[g][3]);
                }
        }
        __syncthreads();
    }

    // epilogue: bias + store
    int rbase = mtile * 128 + wm * 32 + (lane >> 2);
    int cbase = nhalf * 128 + wn * 64 + (lane & 3) * 2;
    #pragma unroll
    for (int mt = 0; mt < 2; ++mt) {
        #pragma unroll
        for (int nt = 0; nt < 8; ++nt) {
            int row = rbase + mt * 16;
            int col = cbase + nt * 8;
            float b0 = bias[col], b1 = bias[col + 1];
            float2 v;
            v.x = acc[mt][nt][0] + b0; v.y = acc[mt][nt][1] + b1;
            *(float2*)(out + (size_t)row * D + col) = v;
            v.x = acc[mt][nt][2] + b0; v.y = acc[mt][nt][3] + b1;
            *(float2*)(out + (size_t)(row + 8) * D + col) = v;
        }
    }
}

// ---------------------------------------------------------------------------
extern "C" void kernel_launch(void* const* d_in, const int* in_sizes, int n_in,
                              void* d_out, int out_size) {
    const float* x     = (const float*)d_in[0];
    const float* comp  = (const float*)d_in[1];
    const float* basis = (const float*)d_in[2];
    const float* root  = (const float*)d_in[3];
    const float* bias  = (const float*)d_in[4];
    float* out = (float*)d_out;

    cudaFuncSetAttribute(gemm_hmma, cudaFuncAttributeMaxDynamicSharedMemorySize, GEMM_SMEM);

    colsum_part<<<dim3(BATCH, PART), D>>>(x);
    colsum_reduce<<<BATCH, D>>>();
    convert_w<<<KC, D>>>(basis, root);
    build_z_pack<<<dim3(S, BATCH), D>>>(x, comp);
    gemm_hmma<<<dim3(2, MTILES), 256, GEMM_SMEM>>>(bias, out);
}

// round 4
// speedup vs baseline: 3.2923x; 1.5458x over previous
#include <cuda_runtime.h>
#include <cuda_fp16.h>
#include <cstdint>

#define D     256
#define S     2048
#define BATCH 8
#define M_TOTAL (BATCH * S)   // 16384
#define KC    (3 * D)         // 768
#define PART  16

#define NCHUNK 12                 // K chunks of 64
#define ACH    16384              // A chunk: hi 128x64 fp16 (swizzled)
#define BCH    65536              // B chunk: [hi 256x64][lo 256x64] fp16
#define MTILES (M_TOTAL / 128)    // 128
#define STAGE_BYTES (ACH + BCH)   // 81920
#define GEMM_SMEM (2 * STAGE_BYTES)  // 163840

// ---------------- scratch (static device globals) ----------------
__device__ float g_part[BATCH][PART][D];
__device__ float g_total[BATCH][D];
__device__ __align__(16) unsigned char g_A[(size_t)MTILES * NCHUNK * ACH];  // 24 MB
__device__ __align__(16) unsigned char g_B[(size_t)NCHUNK * BCH];           // 768 KB

// ---------------- helpers ----------------
__device__ __forceinline__ uint32_t smem_u32(const void* p) {
    uint32_t a;
    asm("{ .reg .u64 t; cvta.to.shared.u64 t, %1; cvt.u32.u64 %0, t; }" : "=r"(a) : "l"(p));
    return a;
}

// swizzled byte offset inside a [rows x 64] fp16 block (row stride 128B)
__device__ __forceinline__ uint32_t swoff(int row, int kk) {
    return (uint32_t)(row * 128 + ((((kk >> 3) ^ (row & 7)) << 4)) + (kk & 7) * 2);
}

__device__ __forceinline__ void cp16(uint32_t dst, const void* src) {
    asm volatile("cp.async.cg.shared.global [%0], [%1], 16;"
        :: "r"(dst), "l"(__cvta_generic_to_global(src)));
}

__device__ __forceinline__ void ldm_x4(uint32_t addr, uint32_t* f) {
    asm volatile("ldmatrix.sync.aligned.m8n8.x4.shared.b16 {%0,%1,%2,%3}, [%4];"
        : "=r"(f[0]), "=r"(f[1]), "=r"(f[2]), "=r"(f[3]) : "r"(addr));
}

__device__ __forceinline__ uint32_t a_addr(uint32_t base, int r0, int k0, int lane) {
    int i = lane & 7, seg = lane >> 3;
    int row = r0 + i + ((seg & 1) << 3);
    int kk = k0 + ((seg >> 1) << 3);
    return base + (uint32_t)(row * 128) + ((((kk >> 3) ^ (row & 7)) << 4));
}
__device__ __forceinline__ uint32_t b_addr(uint32_t base, int n0, int k0, int lane) {
    int i = lane & 7, seg = lane >> 3;
    int row = n0 + i + ((seg >> 1) << 3);
    int kk = k0 + ((seg & 1) << 3);
    return base + (uint32_t)(row * 128) + ((((kk >> 3) ^ (row & 7)) << 4));
}

__device__ __forceinline__ void mma16816(float* c, const uint32_t* a, uint32_t b0, uint32_t b1) {
    asm volatile("mma.sync.aligned.m16n8k16.row.col.f32.f16.f16.f32 "
        "{%0,%1,%2,%3}, {%4,%5,%6,%7}, {%8,%9}, {%0,%1,%2,%3};"
        : "+f"(c[0]), "+f"(c[1]), "+f"(c[2]), "+f"(c[3])
        : "r"(a[0]), "r"(a[1]), "r"(a[2]), "r"(a[3]), "r"(b0), "r"(b1));
}

// ---------------------------------------------------------------------------
// Kernel 1: column sums (two-stage, deterministic)
// ---------------------------------------------------------------------------
__global__ void colsum_part(const float* __restrict__ x) {
    int b = blockIdx.x, p = blockIdx.y, i = threadIdx.x;
    const int chunk = S / PART;
    const float* xp = x + ((long)b * S + (long)p * chunk) * D + i;
    float acc = 0.f;
    #pragma unroll 8
    for (int s = 0; s < chunk; ++s) acc += xp[(long)s * D];
    g_part[b][p][i] = acc;
}
__global__ void colsum_reduce() {
    int b = blockIdx.x, i = threadIdx.x;
    float acc = 0.f;
    #pragma unroll
    for (int p = 0; p < PART; ++p) acc += g_part[b][p][i];
    g_total[b][i] = acc;
}

// ---------------------------------------------------------------------------
// Kernel 2: build z = [z0 | z1 | x], fp16 hi only, 2 elems/thread, half2 stores
// ---------------------------------------------------------------------------
__global__ void __launch_bounds__(128)
build_z_pack(const float* __restrict__ x, const float* __restrict__ comp) {
    int t = blockIdx.x, b = blockIdx.y, tid = threadIdx.x;
    int i = tid * 2;
    const float* xb = x + (long)b * S * D;

    float2 zero2 = make_float2(0.f, 0.f);
    float2 xm1 = (t >= 1)    ? *(const float2*)(xb + (long)(t - 1) * D + i) : zero2;
    float2 x0  =               *(const float2*)(xb + (long)t       * D + i);
    float2 xp1 = (t + 1 < S) ? *(const float2*)(xb + (long)(t + 1) * D + i) : zero2;
    float2 xp2 = (t + 2 < S) ? *(const float2*)(xb + (long)(t + 2) * D + i) : zero2;
    float2 xp3 = (t + 3 < S) ? *(const float2*)(xb + (long)(t + 3) * D + i) : zero2;
    float2 tot = *(const float2*)(&g_total[b][i]);

    int cnt = 1 + (t >= 1) + (t + 1 < S) + (t + 2 < S) + (t + 3 < S);
    float inv1 = 1.f / (1.f + (float)(t + 2 < S));
    int n2i = (t >= 1) + (t + 3 < S);
    float inv2 = n2i ? 1.f / (float)n2i : 0.f;
    float inv3 = 1.f / (float)(S - cnt);
    float c00 = comp[0], c10 = comp[2], c20 = comp[4], c30 = comp[6];
    float c01 = comp[1], c11 = comp[3], c21 = comp[5], c31 = comp[7];

    float z0x, z0y, z1x, z1y;
    {
        float wsum = xm1.x + x0.x + xp1.x + xp2.x + xp3.x;
        float a0 = xp1.x, a1 = (x0.x + xp2.x) * inv1;
        float a2 = (xm1.x + xp3.x) * inv2, a3 = (tot.x - wsum) * inv3;
        z0x = c00 * a0 + c10 * a1 + c20 * a2 + c30 * a3;
        z1x = c01 * a0 + c11 * a1 + c21 * a2 + c31 * a3;
    }
    {
        float wsum = xm1.y + x0.y + xp1.y + xp2.y + xp3.y;
        float a0 = xp1.y, a1 = (x0.y + xp2.y) * inv1;
        float a2 = (xm1.y + xp3.y) * inv2, a3 = (tot.y - wsum) * inv3;
        z0y = c00 * a0 + c10 * a1 + c20 * a2 + c30 * a3;
        z1y = c01 * a0 + c11 * a1 + c21 * a2 + c31 * a3;
    }

    int m = b * S + t;
    int mtile = m >> 7, r = m & 127;
    unsigned char* tb = g_A + (size_t)(mtile * NCHUNK) * ACH;

    // z0 at k=i (chunks 0-3), z1 at k=256+i (4-7), x at k=512+i (8-11)
    int ch = i >> 6, kk = i & 63;
    *(__half2*)(tb + (size_t)ch * ACH + swoff(r, kk)) =
        __floats2half2_rn(z0x, z0y);
    *(__half2*)(tb + (size_t)(ch + 4) * ACH + swoff(r, kk)) =
        __floats2half2_rn(z1x, z1y);
    *(__half2*)(tb + (size_t)(ch + 8) * ACH + swoff(r, kk)) =
        __floats2half2_rn(x0.x, x0.y);
}

// ---------------------------------------------------------------------------
// Kernel 3: pack weights W[k][n] -> g_B[chunk][hi|lo][n 256][k 64], swizzled
// ---------------------------------------------------------------------------
__global__ void convert_w(const float* __restrict__ basis, const float* __restrict__ root) {
    int k = blockIdx.x;          // 0..767
    int n = threadIdx.x;         // 0..255
    float v = (k < 2 * D) ? basis[(size_t)k * D + n] : root[(size_t)(k - 2 * D) * D + n];
    int chunk = k >> 6, kk = k & 63;
    unsigned char* blk = g_B + (size_t)chunk * BCH;
    __half h = __float2half_rn(v);
    __half l = __float2half_rn(v - __half2float(h));
    uint32_t o = swoff(n, kk);
    *(__half*)(blk + o) = h;
    *(__half*)(blk + 32768 + o) = l;
}

// ---------------------------------------------------------------------------
// Kernel 4: HMMA GEMM  out[16384,256] = z @ W + bias  (2-pass: Ah*Bh + Ah*Bl)
// grid 128 (mtile), 512 threads, CTA tile 128x256, warp tile 32x64, BK=64
// ---------------------------------------------------------------------------
__device__ __forceinline__ void load_stage(uint32_t s, const unsigned char* A,
                                           const unsigned char* B, int tid) {
    uint32_t off = (uint32_t)tid * 16;
    cp16(s + off, A + off);
    cp16(s + 8192 + off, A + 8192 + off);
    #pragma unroll
    for (int i = 0; i < 8; ++i)
        cp16(s + ACH + off + (uint32_t)i * 8192, B + off + (uint32_t)i * 8192);
}

__global__ void __launch_bounds__(512, 1)
gemm_hmma(const float* __restrict__ bias, float* __restrict__ out) {
    extern __shared__ unsigned char smem[];
    uint32_t sbase = smem_u32(smem);
    int tid = threadIdx.x, lane = tid & 31, wid = tid >> 5;
    int wm = wid >> 2, wn = wid & 3;      // 4x4 warp grid; warp tile 32 x 64
    int mtile = blockIdx.x;

    const unsigned char* Asrc = g_A + (size_t)(mtile * NCHUNK) * ACH;

    load_stage(sbase, Asrc, g_B, tid);
    asm volatile("cp.async.commit_group;");

    float acc[2][8][4];
    #pragma unroll
    for (int mt = 0; mt < 2; ++mt)
        #pragma unroll
        for (int nt = 0; nt < 8; ++nt)
            #pragma unroll
            for (int q = 0; q < 4; ++q) acc[mt][nt][q] = 0.f;

    for (int c = 0; c < NCHUNK; ++c) {
        if (c + 1 < NCHUNK) {
            load_stage(sbase + (uint32_t)((c + 1) & 1) * STAGE_BYTES,
                       Asrc + (size_t)(c + 1) * ACH, g_B + (size_t)(c + 1) * BCH, tid);
            asm volatile("cp.async.commit_group;");
            asm volatile("cp.async.wait_group 1;");
        } else {
            asm volatile("cp.async.wait_group 0;");
        }
        __syncthreads();

        uint32_t st = sbase + (uint32_t)(c & 1) * STAGE_BYTES;
        uint32_t Ah = st, Bh = st + ACH, Bl = st + ACH + 32768;

        #pragma unroll
        for (int k16 = 0; k16 < 4; ++k16) {
            int k0 = k16 * 16;
            uint32_t ah[2][4];
            #pragma unroll
            for (int mt = 0; mt < 2; ++mt)
                ldm_x4(a_addr(Ah, wm * 32 + mt * 16, k0, lane), ah[mt]);
            #pragma unroll
            for (int g = 0; g < 4; ++g) {
                uint32_t bh[4], bl[4];
                ldm_x4(b_addr(Bh, wn * 64 + g * 16, k0, lane), bh);
                ldm_x4(b_addr(Bl, wn * 64 + g * 16, k0, lane), bl);
                #pragma unroll
                for (int mt = 0; mt < 2; ++mt) {
                    mma16816(acc[mt][2 * g],     ah[mt], bh[0], bh[1]);
                    mma16816(acc[mt][2 * g + 1], ah[mt], bh[2], bh[3]);
                    mma16816(acc[mt][2 * g],     ah[mt], bl[0], bl[1]);
                    mma16816(acc[mt][2 * g + 1], ah[mt], bl[2], bl[3]);
                }
            }
        }
        __syncthreads();
    }

    // epilogue: bias + store
    int rbase = mtile * 128 + wm * 32 + (lane >> 2);
    int cbase = wn * 64 + (lane & 3) * 2;
    #pragma unroll
    for (int mt = 0; mt < 2; ++mt) {
        #pragma unroll
        for (int nt = 0; nt < 8; ++nt) {
            int row = rbase + mt * 16;
            int col = cbase + nt * 8;
            float b0 = bias[col], b1 = bias[col + 1];
            float2 v;
            v.x = acc[mt][nt][0] + b0; v.y = acc[mt][nt][1] + b1;
            *(float2*)(out + (size_t)row * D + col) = v;
            v.x = acc[mt][nt][2] + b0; v.y = acc[mt][nt][3] + b1;
            *(float2*)(out + (size_t)(row + 8) * D + col) = v;
        }
    }
}

// ---------------------------------------------------------------------------
extern "C" void kernel_launch(void* const* d_in, const int* in_sizes, int n_in,
                              void* d_out, int out_size) {
    const float* x     = (const float*)d_in[0];
    const float* comp  = (const float*)d_in[1];
    const float* basis = (const float*)d_in[2];
    const float* root  = (const float*)d_in[3];
    const float* bias  = (const float*)d_in[4];
    float* out = (float*)d_out;

    cudaFuncSetAttribute(gemm_hmma, cudaFuncAttributeMaxDynamicSharedMemorySize, GEMM_SMEM);

    colsum_part<<<dim3(BATCH, PART), D>>>(x);
    colsum_reduce<<<BATCH, D>>>();
    convert_w<<<KC, D>>>(basis, root);
    build_z_pack<<<dim3(S, BATCH), 128>>>(x, comp);
    gemm_hmma<<<MTILES, 512, GEMM_SMEM>>>(bias, out);
}

// round 5
// speedup vs baseline: 4.8160x; 1.4628x over previous
#include <cuda_runtime.h>
#include <cuda_fp16.h>
#include <cstdint>

#define D     256
#define S     2048
#define BATCH 8
#define M_TOTAL (BATCH * S)   // 16384
#define KC    (3 * D)         // 768
#define PART  32

#define NCHUNK 12                 // K chunks of 64
#define ACH    16384              // A chunk: 128x64 fp16 (swizzled)
#define BCH    32768              // B chunk: 256x64 fp16 (swizzled)
#define MTILES (M_TOTAL / 128)    // 128
#define STAGE_BYTES (ACH + BCH)   // 49152
#define NSTAGE 4
#define GEMM_SMEM (NSTAGE * STAGE_BYTES)  // 196608

// ---------------- scratch (static device globals) ----------------
__device__ float g_part[BATCH][PART][D];
__device__ float g_total[BATCH][D];
__device__ __align__(16) unsigned char g_A[(size_t)MTILES * NCHUNK * ACH];  // 24 MB
__device__ __align__(16) unsigned char g_B[(size_t)NCHUNK * BCH];           // 384 KB

// ---------------- helpers ----------------
__device__ __forceinline__ uint32_t smem_u32(const void* p) {
    uint32_t a;
    asm("{ .reg .u64 t; cvta.to.shared.u64 t, %1; cvt.u32.u64 %0, t; }" : "=r"(a) : "l"(p));
    return a;
}

// swizzled byte offset inside a [rows x 64] fp16 block (row stride 128B)
__device__ __forceinline__ uint32_t swoff(int row, int kk) {
    return (uint32_t)(row * 128 + ((((kk >> 3) ^ (row & 7)) << 4)) + (kk & 7) * 2);
}

__device__ __forceinline__ void cp16(uint32_t dst, const void* src) {
    asm volatile("cp.async.cg.shared.global [%0], [%1], 16;"
        :: "r"(dst), "l"(__cvta_generic_to_global(src)));
}

__device__ __forceinline__ void ldm_x4(uint32_t addr, uint32_t* f) {
    asm volatile("ldmatrix.sync.aligned.m8n8.x4.shared.b16 {%0,%1,%2,%3}, [%4];"
        : "=r"(f[0]), "=r"(f[1]), "=r"(f[2]), "=r"(f[3]) : "r"(addr));
}

__device__ __forceinline__ uint32_t a_addr(uint32_t base, int r0, int k0, int lane) {
    int i = lane & 7, seg = lane >> 3;
    int row = r0 + i + ((seg & 1) << 3);
    int kk = k0 + ((seg >> 1) << 3);
    return base + (uint32_t)(row * 128) + ((((kk >> 3) ^ (row & 7)) << 4));
}
__device__ __forceinline__ uint32_t b_addr(uint32_t base, int n0, int k0, int lane) {
    int i = lane & 7, seg = lane >> 3;
    int row = n0 + i + ((seg >> 1) << 3);
    int kk = k0 + ((seg & 1) << 3);
    return base + (uint32_t)(row * 128) + ((((kk >> 3) ^ (row & 7)) << 4));
}

__device__ __forceinline__ void mma16816(float* c, const uint32_t* a, uint32_t b0, uint32_t b1) {
    asm volatile("mma.sync.aligned.m16n8k16.row.col.f32.f16.f16.f32 "
        "{%0,%1,%2,%3}, {%4,%5,%6,%7}, {%8,%9}, {%0,%1,%2,%3};"
        : "+f"(c[0]), "+f"(c[1]), "+f"(c[2]), "+f"(c[3])
        : "r"(a[0]), "r"(a[1]), "r"(a[2]), "r"(a[3]), "r"(b0), "r"(b1));
}

__device__ __forceinline__ uint2 pack_half4(const float* v) {
    __half2 lo = __floats2half2_rn(v[0], v[1]);
    __half2 hi = __floats2half2_rn(v[2], v[3]);
    uint2 u;
    u.x = *(const uint32_t*)&lo;
    u.y = *(const uint32_t*)&hi;
    return u;
}

// ---------------------------------------------------------------------------
// Kernel 1: column sums (two-stage, deterministic, float4)
// ---------------------------------------------------------------------------
__global__ void __launch_bounds__(128)
colsum_part(const float* __restrict__ x) {
    int b = blockIdx.x, p = blockIdx.y, tid = threadIdx.x;
    int c4 = (tid & 63) * 4;       // column group
    int rh = tid >> 6;             // 0/1 row half
    const int chunk = S / PART;    // 64
    const int half = chunk / 2;    // 32
    const float* xp = x + ((long)b * S + (long)(p * chunk + rh * half)) * D + c4;
    float a0 = 0.f, a1 = 0.f, a2 = 0.f, a3 = 0.f;
    #pragma unroll 8
    for (int s = 0; s < half; ++s) {
        float4 v = *(const float4*)(xp + (long)s * D);
        a0 += v.x; a1 += v.y; a2 += v.z; a3 += v.w;
    }
    __shared__ float4 sh[64];
    if (rh == 1) sh[tid & 63] = make_float4(a0, a1, a2, a3);
    __syncthreads();
    if (rh == 0) {
        float4 o = sh[tid & 63];
        float4 r = make_float4(a0 + o.x, a1 + o.y, a2 + o.z, a3 + o.w);
        *(float4*)(&g_part[b][p][c4]) = r;
    }
}
__global__ void __launch_bounds__(64)
colsum_reduce() {
    int b = blockIdx.x, c4 = threadIdx.x * 4;
    float a0 = 0.f, a1 = 0.f, a2 = 0.f, a3 = 0.f;
    #pragma unroll
    for (int p = 0; p < PART; ++p) {
        float4 v = *(const float4*)(&g_part[b][p][c4]);
        a0 += v.x; a1 += v.y; a2 += v.z; a3 += v.w;
    }
    *(float4*)(&g_total[b][c4]) = make_float4(a0, a1, a2, a3);
}

// ---------------------------------------------------------------------------
// Kernel 2: build z = [z0 | z1 | x], fp16, 4 elems/thread, 2 rows/block
// ---------------------------------------------------------------------------
__global__ void __launch_bounds__(128)
build_z_pack(const float* __restrict__ x, const float* __restrict__ comp) {
    int b = blockIdx.y, tid = threadIdx.x;
    int t = blockIdx.x * 2 + (tid >> 6);
    int i = (tid & 63) * 4;
    const float* xb = x + (long)b * S * D;

    float xm1[4] = {0,0,0,0}, x0[4], xp1[4] = {0,0,0,0}, xp2[4] = {0,0,0,0}, xp3[4] = {0,0,0,0}, tot[4];
    if (t >= 1)    *(float4*)xm1 = *(const float4*)(xb + (long)(t - 1) * D + i);
    *(float4*)x0 = *(const float4*)(xb + (long)t * D + i);
    if (t + 1 < S) *(float4*)xp1 = *(const float4*)(xb + (long)(t + 1) * D + i);
    if (t + 2 < S) *(float4*)xp2 = *(const float4*)(xb + (long)(t + 2) * D + i);
    if (t + 3 < S) *(float4*)xp3 = *(const float4*)(xb + (long)(t + 3) * D + i);
    *(float4*)tot = *(const float4*)(&g_total[b][i]);

    int cnt = 1 + (t >= 1) + (t + 1 < S) + (t + 2 < S) + (t + 3 < S);
    float inv1 = 1.f / (1.f + (float)(t + 2 < S));
    int n2i = (t >= 1) + (t + 3 < S);
    float inv2 = n2i ? 1.f / (float)n2i : 0.f;
    float inv3 = 1.f / (float)(S - cnt);
    float c00 = comp[0], c10 = comp[2], c20 = comp[4], c30 = comp[6];
    float c01 = comp[1], c11 = comp[3], c21 = comp[5], c31 = comp[7];

    float z0[4], z1[4];
    #pragma unroll
    for (int j = 0; j < 4; ++j) {
        float wsum = xm1[j] + x0[j] + xp1[j] + xp2[j] + xp3[j];
        float a0 = xp1[j];
        float a1 = (x0[j] + xp2[j]) * inv1;
        float a2 = (xm1[j] + xp3[j]) * inv2;
        float a3 = (tot[j] - wsum) * inv3;
        z0[j] = c00 * a0 + c10 * a1 + c20 * a2 + c30 * a3;
        z1[j] = c01 * a0 + c11 * a1 + c21 * a2 + c31 * a3;
    }

    int m = b * S + t;
    int mtile = m >> 7, r = m & 127;
    unsigned char* tb = g_A + (size_t)(mtile * NCHUNK) * ACH;
    int ch = i >> 6, kk = i & 63;
    uint32_t o = swoff(r, kk);
    *(uint2*)(tb + (size_t)ch * ACH + o)       = pack_half4(z0);
    *(uint2*)(tb + (size_t)(ch + 4) * ACH + o) = pack_half4(z1);
    *(uint2*)(tb + (size_t)(ch + 8) * ACH + o) = pack_half4(x0);
}

// ---------------------------------------------------------------------------
// Kernel 3: pack weights W[k][n] -> g_B[chunk][n 256][k 64], fp16, swizzled
// ---------------------------------------------------------------------------
__global__ void convert_w(const float* __restrict__ basis, const float* __restrict__ root) {
    int k = blockIdx.x;          // 0..767
    int n = threadIdx.x;         // 0..255
    float v = (k < 2 * D) ? basis[(size_t)k * D + n] : root[(size_t)(k - 2 * D) * D + n];
    int chunk = k >> 6, kk = k & 63;
    *(__half*)(g_B + (size_t)chunk * BCH + swoff(n, kk)) = __float2half_rn(v);
}

// ---------------------------------------------------------------------------
// Kernel 4: HMMA GEMM  out[16384,256] = z @ W + bias  (1 pass, 4 stages)
// grid 128 (mtile), 512 threads, CTA tile 128x256, warp tile 32x64, BK=64
// ---------------------------------------------------------------------------
__device__ __forceinline__ void load_stage(uint32_t s, const unsigned char* A,
                                           const unsigned char* B, int tid) {
    uint32_t off = (uint32_t)tid * 16;
    cp16(s + off, A + off);
    cp16(s + 8192 + off, A + 8192 + off);
    #pragma unroll
    for (int i = 0; i < 4; ++i)
        cp16(s + ACH + off + (uint32_t)i * 8192, B + off + (uint32_t)i * 8192);
}

__global__ void __launch_bounds__(512, 1)
gemm_hmma(const float* __restrict__ bias, float* __restrict__ out) {
    extern __shared__ unsigned char smem[];
    uint32_t sbase = smem_u32(smem);
    int tid = threadIdx.x, lane = tid & 31, wid = tid >> 5;
    int wm = wid >> 2, wn = wid & 3;      // 4x4 warp grid; warp tile 32 x 64
    int mtile = blockIdx.x;

    const unsigned char* Asrc = g_A + (size_t)(mtile * NCHUNK) * ACH;

    #pragma unroll
    for (int s = 0; s < NSTAGE - 1; ++s) {
        load_stage(sbase + (uint32_t)s * STAGE_BYTES,
                   Asrc + (size_t)s * ACH, g_B + (size_t)s * BCH, tid);
        asm volatile("cp.async.commit_group;");
    }

    float acc[2][8][4];
    #pragma unroll
    for (int mt = 0; mt < 2; ++mt)
        #pragma unroll
        for (int nt = 0; nt < 8; ++nt)
            #pragma unroll
            for (int q = 0; q < 4; ++q) acc[mt][nt][q] = 0.f;

    for (int c = 0; c < NCHUNK; ++c) {
        if (c + NSTAGE - 1 < NCHUNK) {
            int cn = c + NSTAGE - 1;
            load_stage(sbase + (uint32_t)(cn & (NSTAGE - 1)) * STAGE_BYTES,
                       Asrc + (size_t)cn * ACH, g_B + (size_t)cn * BCH, tid);
            asm volatile("cp.async.commit_group;");
        }
        if (c <= NCHUNK - NSTAGE)      asm volatile("cp.async.wait_group 3;");
        else if (c == NCHUNK - 3)      asm volatile("cp.async.wait_group 2;");
        else if (c == NCHUNK - 2)      asm volatile("cp.async.wait_group 1;");
        else                           asm volatile("cp.async.wait_group 0;");
        __syncthreads();

        uint32_t st = sbase + (uint32_t)(c & (NSTAGE - 1)) * STAGE_BYTES;
        uint32_t Ah = st, Bh = st + ACH;

        #pragma unroll
        for (int k16 = 0; k16 < 4; ++k16) {
            int k0 = k16 * 16;
            uint32_t ah[2][4];
            #pragma unroll
            for (int mt = 0; mt < 2; ++mt)
                ldm_x4(a_addr(Ah, wm * 32 + mt * 16, k0, lane), ah[mt]);
            #pragma unroll
            for (int g = 0; g < 4; ++g) {
                uint32_t bh[4];
                ldm_x4(b_addr(Bh, wn * 64 + g * 16, k0, lane), bh);
                #pragma unroll
                for (int mt = 0; mt < 2; ++mt) {
                    mma16816(acc[mt][2 * g],     ah[mt], bh[0], bh[1]);
                    mma16816(acc[mt][2 * g + 1], ah[mt], bh[2], bh[3]);
                }
            }
        }
        __syncthreads();
    }

    // epilogue: bias + store
    int rbase = mtile * 128 + wm * 32 + (lane >> 2);
    int cbase = wn * 64 + (lane & 3) * 2;
    #pragma unroll
    for (int mt = 0; mt < 2; ++mt) {
        #pragma unroll
        for (int nt = 0; nt < 8; ++nt) {
            int row = rbase + mt * 16;
            int col = cbase + nt * 8;
            float b0 = bias[col], b1 = bias[col + 1];
            float2 v;
            v.x = acc[mt][nt][0] + b0; v.y = acc[mt][nt][1] + b1;
            *(float2*)(out + (size_t)row * D + col) = v;
            v.x = acc[mt][nt][2] + b0; v.y = acc[mt][nt][3] + b1;
            *(float2*)(out + (size_t)(row + 8) * D + col) = v;
        }
    }
}

// ---------------------------------------------------------------------------
extern "C" void kernel_launch(void* const* d_in, const int* in_sizes, int n_in,
                              void* d_out, int out_size) {
    const float* x     = (const float*)d_in[0];
    const float* comp  = (const float*)d_in[1];
    const float* basis = (const float*)d_in[2];
    const float* root  = (const float*)d_in[3];
    const float* bias  = (const float*)d_in[4];
    float* out = (float*)d_out;

    cudaFuncSetAttribute(gemm_hmma, cudaFuncAttributeMaxDynamicSharedMemorySize, GEMM_SMEM);

    convert_w<<<KC, D>>>(basis, root);
    colsum_part<<<dim3(BATCH, PART), 128>>>(x);
    colsum_reduce<<<BATCH, 64>>>();
    build_z_pack<<<dim3(S / 2, BATCH), 128>>>(x, comp);
    gemm_hmma<<<MTILES, 512, GEMM_SMEM>>>(bias, out);
}